// round 1
// baseline (speedup 1.0000x reference)
#include <cuda_runtime.h>

// ---------------------------------------------------------------------------
// MHA block: QKV proj -> flash attention -> O proj (+residual) -> LayerNorm
// B=2, T=2048, H=1024, 16 heads x 64 dim. All fp32 (FFMA baseline).
// ---------------------------------------------------------------------------

#define QKV_ELEMS (2*16*2048*64)   // 4,194,304
#define ROW_ELEMS (4096*1024)      // 4,194,304

__device__ float g_Q[QKV_ELEMS];
__device__ float g_K[QKV_ELEMS];
__device__ float g_V[QKV_ELEMS];
__device__ float g_ctx[ROW_ELEMS];
__device__ float g_tmp[ROW_ELEMS];

__device__ __forceinline__ float ex2f(float x) {
    float y;
    asm("ex2.approx.ftz.f32 %0, %1;" : "=f"(y) : "f"(x));
    return y;
}

// ---------------------------------------------------------------------------
// NT GEMM: C[M,N] = A[M,K] @ B[N,K]^T + bias[N]   (K = 1024)
// MODE 0: scatter-write into [b, head, t, d] layout (QKV projections)
// MODE 1: row-major write with fused residual add (output projection)
// Block tile 128x128x16, 256 threads, 8x8 per thread.
// ---------------------------------------------------------------------------
template<int MODE>
__global__ __launch_bounds__(256) void gemm_nt(
    const float* __restrict__ A, const float* __restrict__ B,
    const float* __restrict__ bias, const float* __restrict__ resid,
    float* __restrict__ C)
{
    const int K = 1024;
    __shared__ float As[16][128];
    __shared__ float Bs[16][128];
    const int m0 = blockIdx.y * 128;
    const int n0 = blockIdx.x * 128;
    const int tid = threadIdx.x;
    const int tx = tid & 15, ty = tid >> 4;

    float acc[8][8];
#pragma unroll
    for (int i = 0; i < 8; i++)
#pragma unroll
        for (int j = 0; j < 8; j++) acc[i][j] = 0.f;

    for (int k0 = 0; k0 < K; k0 += 16) {
#pragma unroll
        for (int i = 0; i < 2; i++) {
            int idx = tid + i * 256;
            int row = idx >> 2;           // 0..127
            int kq  = (idx & 3) << 2;     // 0,4,8,12
            float4 av = *(const float4*)(A + (size_t)(m0 + row) * K + k0 + kq);
            float4 bv = *(const float4*)(B + (size_t)(n0 + row) * K + k0 + kq);
            As[kq + 0][row] = av.x; As[kq + 1][row] = av.y;
            As[kq + 2][row] = av.z; As[kq + 3][row] = av.w;
            Bs[kq + 0][row] = bv.x; Bs[kq + 1][row] = bv.y;
            Bs[kq + 2][row] = bv.z; Bs[kq + 3][row] = bv.w;
        }
        __syncthreads();
#pragma unroll
        for (int k = 0; k < 16; k++) {
            float a[8], b[8];
            *(float4*)(a)     = *(const float4*)(&As[k][ty * 8]);
            *(float4*)(a + 4) = *(const float4*)(&As[k][ty * 8 + 4]);
            *(float4*)(b)     = *(const float4*)(&Bs[k][tx * 8]);
            *(float4*)(b + 4) = *(const float4*)(&Bs[k][tx * 8 + 4]);
#pragma unroll
            for (int i = 0; i < 8; i++)
#pragma unroll
                for (int j = 0; j < 8; j++)
                    acc[i][j] = fmaf(a[i], b[j], acc[i][j]);
        }
        __syncthreads();
    }

#pragma unroll
    for (int i = 0; i < 8; i++) {
        int m = m0 + ty * 8 + i;
#pragma unroll
        for (int j = 0; j < 8; j++) {
            int n = n0 + tx * 8 + j;
            float v = acc[i][j] + bias[n];
            if (MODE == 0) {
                int b  = m >> 11;      // batch
                int t  = m & 2047;     // time
                int hh = n >> 6;       // head
                int dd = n & 63;       // dim
                C[(((size_t)(b * 16 + hh)) * 2048 + t) * 64 + dd] = v;
            } else {
                size_t o = (size_t)m * 1024 + n;
                C[o] = v + resid[o];
            }
        }
    }
}

// ---------------------------------------------------------------------------
// Flash attention. Grid: (32 q-tiles, 32 batch*head). 256 threads.
// Q tile 64x64 held in smem (scaled by 1/sqrt(d)*log2(e) at load, so softmax
// is a single ex2 per element). Online softmax with 4x4 register tiles.
// Smem: Qt (transposed+swizzled), KP (K transposed+swizzled, then reused for
// P row-major), Vs (row-major). Total 48 KB static.
// ---------------------------------------------------------------------------
#define SCL 0.18033688011112042f   // (1/8) * log2(e)

__global__ __launch_bounds__(256) void attn_kernel()
{
    __shared__ float Qt[64 * 64];
    __shared__ float KP[64 * 64];
    __shared__ float Vs[64 * 64];

    const int bh = blockIdx.y;
    const int q0 = blockIdx.x * 64;
    const float* Qg = g_Q + ((size_t)bh * 2048 + q0) * 64;
    const float* Kb = g_K + (size_t)bh * 2048 * 64;
    const float* Vb = g_V + (size_t)bh * 2048 * 64;

    const int tid = threadIdx.x;
    const int tx = tid & 15, ty = tid >> 4;
    const int tx4 = tx * 4, ty4 = ty * 4;

    // Load Q transposed with XOR swizzle: element (d, r) -> Qt[d*64 + (r ^ (d&60))]
#pragma unroll
    for (int i = 0; i < 4; i++) {
        int idx = tid + i * 256;
        int r  = idx >> 4;            // 0..63
        int d0 = (idx & 15) << 2;     // 0..60
        float4 v = *(const float4*)(Qg + r * 64 + d0);
        int col = r ^ d0;             // d0 == (d & 60) for all 4 lanes of the vec
        Qt[(d0 + 0) * 64 + col] = v.x * SCL;
        Qt[(d0 + 1) * 64 + col] = v.y * SCL;
        Qt[(d0 + 2) * 64 + col] = v.z * SCL;
        Qt[(d0 + 3) * 64 + col] = v.w * SCL;
    }

    float m_run[4] = {-1e30f, -1e30f, -1e30f, -1e30f};
    float l_run[4] = {0.f, 0.f, 0.f, 0.f};
    float acc[4][4];
#pragma unroll
    for (int i = 0; i < 4; i++)
#pragma unroll
        for (int j = 0; j < 4; j++) acc[i][j] = 0.f;

    for (int t = 0; t < 32; t++) {
        __syncthreads();  // prior-iter reads of KP(P)/Vs complete
        const float* Kg = Kb + (size_t)t * 64 * 64;
        const float* Vg = Vb + (size_t)t * 64 * 64;
#pragma unroll
        for (int i = 0; i < 4; i++) {
            int idx = tid + i * 256;
            int r  = idx >> 4;
            int d0 = (idx & 15) << 2;
            float4 kv = *(const float4*)(Kg + r * 64 + d0);
            int col = r ^ d0;
            KP[(d0 + 0) * 64 + col] = kv.x;
            KP[(d0 + 1) * 64 + col] = kv.y;
            KP[(d0 + 2) * 64 + col] = kv.z;
            KP[(d0 + 3) * 64 + col] = kv.w;
            float4 vv = *(const float4*)(Vg + r * 64 + d0);
            *(float4*)(&Vs[r * 64 + d0]) = vv;
        }
        __syncthreads();

        // S = (Q * scale*log2e) @ K^T   -> 4x4 per thread
        float s[4][4];
#pragma unroll
        for (int i = 0; i < 4; i++)
#pragma unroll
            for (int j = 0; j < 4; j++) s[i][j] = 0.f;

#pragma unroll 8
        for (int d = 0; d < 64; d++) {
            int base = d * 64;
            int cst  = d & 60;
            float4 k4 = *(const float4*)(&KP[base + (tx4 ^ cst)]);
            float q0v = Qt[base + ((ty4 + 0) ^ cst)];
            float q1v = Qt[base + ((ty4 + 1) ^ cst)];
            float q2v = Qt[base + ((ty4 + 2) ^ cst)];
            float q3v = Qt[base + ((ty4 + 3) ^ cst)];
            s[0][0] = fmaf(q0v, k4.x, s[0][0]); s[0][1] = fmaf(q0v, k4.y, s[0][1]);
            s[0][2] = fmaf(q0v, k4.z, s[0][2]); s[0][3] = fmaf(q0v, k4.w, s[0][3]);
            s[1][0] = fmaf(q1v, k4.x, s[1][0]); s[1][1] = fmaf(q1v, k4.y, s[1][1]);
            s[1][2] = fmaf(q1v, k4.z, s[1][2]); s[1][3] = fmaf(q1v, k4.w, s[1][3]);
            s[2][0] = fmaf(q2v, k4.x, s[2][0]); s[2][1] = fmaf(q2v, k4.y, s[2][1]);
            s[2][2] = fmaf(q2v, k4.z, s[2][2]); s[2][3] = fmaf(q2v, k4.w, s[2][3]);
            s[3][0] = fmaf(q3v, k4.x, s[3][0]); s[3][1] = fmaf(q3v, k4.y, s[3][1]);
            s[3][2] = fmaf(q3v, k4.z, s[3][2]); s[3][3] = fmaf(q3v, k4.w, s[3][3]);
        }

        // Online softmax update (log2 domain).
        float p[4][4];
#pragma unroll
        for (int i = 0; i < 4; i++) {
            float rm = fmaxf(fmaxf(s[i][0], s[i][1]), fmaxf(s[i][2], s[i][3]));
            rm = fmaxf(rm, __shfl_xor_sync(0xffffffffu, rm, 1));
            rm = fmaxf(rm, __shfl_xor_sync(0xffffffffu, rm, 2));
            rm = fmaxf(rm, __shfl_xor_sync(0xffffffffu, rm, 4));
            rm = fmaxf(rm, __shfl_xor_sync(0xffffffffu, rm, 8));
            float mnew  = fmaxf(m_run[i], rm);
            float alpha = ex2f(m_run[i] - mnew);
            m_run[i] = mnew;
            p[i][0] = ex2f(s[i][0] - mnew);
            p[i][1] = ex2f(s[i][1] - mnew);
            p[i][2] = ex2f(s[i][2] - mnew);
            p[i][3] = ex2f(s[i][3] - mnew);
            float rs = p[i][0] + p[i][1] + p[i][2] + p[i][3];
            rs += __shfl_xor_sync(0xffffffffu, rs, 1);
            rs += __shfl_xor_sync(0xffffffffu, rs, 2);
            rs += __shfl_xor_sync(0xffffffffu, rs, 4);
            rs += __shfl_xor_sync(0xffffffffu, rs, 8);
            l_run[i] = l_run[i] * alpha + rs;
            acc[i][0] *= alpha; acc[i][1] *= alpha;
            acc[i][2] *= alpha; acc[i][3] *= alpha;
        }

        __syncthreads();  // everyone done reading K from KP
        // Store P row-major into KP: P[r][c]
#pragma unroll
        for (int i = 0; i < 4; i++)
            *(float4*)(&KP[(ty4 + i) * 64 + tx4]) =
                make_float4(p[i][0], p[i][1], p[i][2], p[i][3]);
        __syncthreads();

        // O += P @ V  -> 4x4 per thread over d columns tx4..tx4+3
#pragma unroll 8
        for (int c = 0; c < 64; c++) {
            float4 v4 = *(const float4*)(&Vs[c * 64 + tx4]);
            float p0 = KP[(ty4 + 0) * 64 + c];
            float p1 = KP[(ty4 + 1) * 64 + c];
            float p2 = KP[(ty4 + 2) * 64 + c];
            float p3 = KP[(ty4 + 3) * 64 + c];
            acc[0][0] = fmaf(p0, v4.x, acc[0][0]); acc[0][1] = fmaf(p0, v4.y, acc[0][1]);
            acc[0][2] = fmaf(p0, v4.z, acc[0][2]); acc[0][3] = fmaf(p0, v4.w, acc[0][3]);
            acc[1][0] = fmaf(p1, v4.x, acc[1][0]); acc[1][1] = fmaf(p1, v4.y, acc[1][1]);
            acc[1][2] = fmaf(p1, v4.z, acc[1][2]); acc[1][3] = fmaf(p1, v4.w, acc[1][3]);
            acc[2][0] = fmaf(p2, v4.x, acc[2][0]); acc[2][1] = fmaf(p2, v4.y, acc[2][1]);
            acc[2][2] = fmaf(p2, v4.z, acc[2][2]); acc[2][3] = fmaf(p2, v4.w, acc[2][3]);
            acc[3][0] = fmaf(p3, v4.x, acc[3][0]); acc[3][1] = fmaf(p3, v4.y, acc[3][1]);
            acc[3][2] = fmaf(p3, v4.z, acc[3][2]); acc[3][3] = fmaf(p3, v4.w, acc[3][3]);
        }
    }

    // Normalize and write ctx[b*T + q][head*64 + d]  (row-major [4096,1024])
    const int b = bh >> 4, hh = bh & 15;
#pragma unroll
    for (int i = 0; i < 4; i++) {
        float inv = 1.0f / l_run[i];
        size_t o = ((size_t)(b * 2048 + q0 + ty4 + i)) * 1024 + hh * 64 + tx4;
        *(float4*)(&g_ctx[o]) = make_float4(acc[i][0] * inv, acc[i][1] * inv,
                                            acc[i][2] * inv, acc[i][3] * inv);
    }
}

// ---------------------------------------------------------------------------
// LayerNorm over rows of 1024. One block per row, 256 threads x float4.
// ---------------------------------------------------------------------------
__global__ __launch_bounds__(256) void ln_kernel(
    const float* __restrict__ x, const float* __restrict__ gamma,
    const float* __restrict__ beta, float* __restrict__ out)
{
    __shared__ float rs[8], rq[8];
    __shared__ float s_mu, s_rstd;
    const int row = blockIdx.x;
    const int tid = threadIdx.x;
    const float* xr = x + (size_t)row * 1024;

    float4 v = *(const float4*)(xr + tid * 4);
    float s = v.x + v.y + v.z + v.w;
    float q = v.x * v.x + v.y * v.y + v.z * v.z + v.w * v.w;
#pragma unroll
    for (int o = 16; o > 0; o >>= 1) {
        s += __shfl_xor_sync(0xffffffffu, s, o);
        q += __shfl_xor_sync(0xffffffffu, q, o);
    }
    if ((tid & 31) == 0) { rs[tid >> 5] = s; rq[tid >> 5] = q; }
    __syncthreads();
    if (tid == 0) {
        float S = 0.f, Q = 0.f;
#pragma unroll
        for (int w = 0; w < 8; w++) { S += rs[w]; Q += rq[w]; }
        float mu  = S * (1.0f / 1024.0f);
        float var = Q * (1.0f / 1024.0f) - mu * mu;
        s_mu   = mu;
        s_rstd = rsqrtf(var + 1e-6f);
    }
    __syncthreads();
    float mu = s_mu, r = s_rstd;
    float4 g  = *(const float4*)(gamma + tid * 4);
    float4 bb = *(const float4*)(beta + tid * 4);
    float4 o4;
    o4.x = (v.x - mu) * r * g.x + bb.x;
    o4.y = (v.y - mu) * r * g.y + bb.y;
    o4.z = (v.z - mu) * r * g.z + bb.z;
    o4.w = (v.w - mu) * r * g.w + bb.w;
    *(float4*)(out + (size_t)row * 1024 + tid * 4) = o4;
}

// ---------------------------------------------------------------------------
// Launch: QKV gemms -> attention -> O gemm (+residual) -> LayerNorm
// ---------------------------------------------------------------------------
extern "C" void kernel_launch(void* const* d_in, const int* in_sizes, int n_in,
                              void* d_out, int out_size)
{
    (void)in_sizes; (void)n_in; (void)out_size;
    const float* h     = (const float*)d_in[0];
    const float* Wq    = (const float*)d_in[1];
    const float* bq    = (const float*)d_in[2];
    const float* Wk    = (const float*)d_in[3];
    const float* bk    = (const float*)d_in[4];
    const float* Wv    = (const float*)d_in[5];
    const float* bv    = (const float*)d_in[6];
    const float* Wo    = (const float*)d_in[7];
    const float* bo    = (const float*)d_in[8];
    const float* gamma = (const float*)d_in[9];
    const float* beta  = (const float*)d_in[10];
    float* out = (float*)d_out;

    float *qp, *kp, *vp, *cp, *tp;
    cudaGetSymbolAddress((void**)&qp, g_Q);
    cudaGetSymbolAddress((void**)&kp, g_K);
    cudaGetSymbolAddress((void**)&vp, g_V);
    cudaGetSymbolAddress((void**)&cp, g_ctx);
    cudaGetSymbolAddress((void**)&tp, g_tmp);

    dim3 gg(1024 / 128, 4096 / 128);  // (8, 32)
    gemm_nt<0><<<gg, 256>>>(h, Wq, bq, nullptr, qp);
    gemm_nt<0><<<gg, 256>>>(h, Wk, bk, nullptr, kp);
    gemm_nt<0><<<gg, 256>>>(h, Wv, bv, nullptr, vp);

    attn_kernel<<<dim3(32, 32), 256>>>();

    gemm_nt<1><<<gg, 256>>>(cp, Wo, bo, h, tp);

    ln_kernel<<<4096, 256>>>(tp, gamma, beta, out);
}

// round 3
// speedup vs baseline: 1.4638x; 1.4638x over previous
#include <cuda_runtime.h>
#include <cuda_bf16.h>
#include <cstdint>

// ---------------------------------------------------------------------------
// MHA block on GB300 (sm_103 baseline PTX -> mma.sync/ldmatrix/cp.async path)
// QKV/O projections: bf16 hi/lo split (3-term) mma.sync GEMM, fp32-accurate.
// Attention: fp32 FFMA flash kernel (next round's target). Fused LayerNorm.
// B=2, T=2048, H=1024, 16 heads x 64 dim.
// ---------------------------------------------------------------------------

#define QKV_ELEMS (2*16*2048*64)   // 4,194,304
#define ROW_ELEMS (4096*1024)      // 4,194,304
#define W_ELEMS   (1024*1024)

__device__ float g_Q[QKV_ELEMS];
__device__ float g_K[QKV_ELEMS];
__device__ float g_V[QKV_ELEMS];
__device__ float g_ctx[ROW_ELEMS];
__device__ float g_tmp[ROW_ELEMS];

// bf16 split arrays
__device__ __nv_bfloat16 g_hh[ROW_ELEMS],  g_hl[ROW_ELEMS];   // h
__device__ __nv_bfloat16 g_ch[ROW_ELEMS],  g_cl[ROW_ELEMS];   // ctx
__device__ __nv_bfloat16 g_wqh[W_ELEMS],   g_wql[W_ELEMS];
__device__ __nv_bfloat16 g_wkh[W_ELEMS],   g_wkl[W_ELEMS];
__device__ __nv_bfloat16 g_wvh[W_ELEMS],   g_wvl[W_ELEMS];
__device__ __nv_bfloat16 g_woh[W_ELEMS],   g_wol[W_ELEMS];

__device__ __forceinline__ float ex2f(float x) {
    float y;
    asm("ex2.approx.ftz.f32 %0, %1;" : "=f"(y) : "f"(x));
    return y;
}

__device__ __forceinline__ uint32_t smem_u32(const void* p) {
    uint32_t a;
    asm("{ .reg .u64 t; cvta.to.shared.u64 t, %1; cvt.u32.u64 %0, t; }"
        : "=r"(a) : "l"(p));
    return a;
}

__device__ __forceinline__ void cp16(uint32_t saddr, const void* g) {
    asm volatile("cp.async.cg.shared.global [%0], [%1], 16;"
                 :: "r"(saddr), "l"(g) : "memory");
}
#define CP_COMMIT() asm volatile("cp.async.commit_group;" ::: "memory")
#define CP_WAIT1()  asm volatile("cp.async.wait_group 1;" ::: "memory")

__device__ __forceinline__ void ldsm4(uint32_t* r, uint32_t addr) {
    asm volatile("ldmatrix.sync.aligned.m8n8.x4.shared.b16 {%0,%1,%2,%3}, [%4];"
                 : "=r"(r[0]), "=r"(r[1]), "=r"(r[2]), "=r"(r[3]) : "r"(addr));
}

__device__ __forceinline__ void mma16816(float* d, const uint32_t* a, const uint32_t* b) {
    asm volatile(
        "mma.sync.aligned.m16n8k16.row.col.f32.bf16.bf16.f32 "
        "{%0,%1,%2,%3}, {%4,%5,%6,%7}, {%8,%9}, {%0,%1,%2,%3};"
        : "+f"(d[0]), "+f"(d[1]), "+f"(d[2]), "+f"(d[3])
        : "r"(a[0]), "r"(a[1]), "r"(a[2]), "r"(a[3]), "r"(b[0]), "r"(b[1]));
}

// ---------------------------------------------------------------------------
// bf16 split: hi = bf16(x), lo = bf16(x - hi). 8 elems/thread, 16B stores.
// ---------------------------------------------------------------------------
__global__ __launch_bounds__(256) void split8(
    const float* __restrict__ x, __nv_bfloat16* __restrict__ hi,
    __nv_bfloat16* __restrict__ lo)
{
    int i = (blockIdx.x * 256 + threadIdx.x) * 8;
    float4 v0 = *(const float4*)(x + i);
    float4 v1 = *(const float4*)(x + i + 4);
    __nv_bfloat162 h0 = __float22bfloat162_rn(make_float2(v0.x, v0.y));
    __nv_bfloat162 h1 = __float22bfloat162_rn(make_float2(v0.z, v0.w));
    __nv_bfloat162 h2 = __float22bfloat162_rn(make_float2(v1.x, v1.y));
    __nv_bfloat162 h3 = __float22bfloat162_rn(make_float2(v1.z, v1.w));
    __nv_bfloat162 l0 = __float22bfloat162_rn(make_float2(v0.x - __low2float(h0), v0.y - __high2float(h0)));
    __nv_bfloat162 l1 = __float22bfloat162_rn(make_float2(v0.z - __low2float(h1), v0.w - __high2float(h1)));
    __nv_bfloat162 l2 = __float22bfloat162_rn(make_float2(v1.x - __low2float(h2), v1.y - __high2float(h2)));
    __nv_bfloat162 l3 = __float22bfloat162_rn(make_float2(v1.z - __low2float(h3), v1.w - __high2float(h3)));
    uint4 ph, pl;
    ph.x = *(uint32_t*)&h0; ph.y = *(uint32_t*)&h1;
    ph.z = *(uint32_t*)&h2; ph.w = *(uint32_t*)&h3;
    pl.x = *(uint32_t*)&l0; pl.y = *(uint32_t*)&l1;
    pl.z = *(uint32_t*)&l2; pl.w = *(uint32_t*)&l3;
    *(uint4*)(hi + i) = ph;
    *(uint4*)(lo + i) = pl;
}

// ---------------------------------------------------------------------------
// mma.sync NT GEMM: C[M,N] = A[M,K] @ W[N,K]^T + bias[N], K = 1024, fp32 via
// 3-term bf16 split: Ah*Wh + Ah*Wl + Al*Wh.
// Block 128x128x32, 256 threads (8 warps, warp tile 32m x 64n), 2-stage
// cp.async double buffer. Swizzle: 16B chunk c at (row,c) -> c ^ ((row>>1)&3).
// MODE 0: scatter into [b, head, t, d] (QKV). MODE 1: row-major + residual.
// ---------------------------------------------------------------------------
#define STG 32768
#define OFF_AL 8192
#define OFF_WH 16384
#define OFF_WL 24576
#define GEMM_SMEM (2 * STG)

__device__ __forceinline__ uint32_t smoff(int row, int c) {
    return row * 64 + ((c ^ ((row >> 1) & 3)) << 4);
}

template<int MODE>
__global__ __launch_bounds__(256)
void gemm_mma(const __nv_bfloat16* __restrict__ Ah, const __nv_bfloat16* __restrict__ Al,
              const __nv_bfloat16* __restrict__ Wh, const __nv_bfloat16* __restrict__ Wl,
              const float* __restrict__ bias, const float* __restrict__ resid,
              float* __restrict__ C)
{
    extern __shared__ char smem[];
    const uint32_t sb = smem_u32(smem);
    const int tid = threadIdx.x;
    const int n0 = blockIdx.x * 128;
    const int m0 = blockIdx.y * 128;
    const int lane = tid & 31, w = tid >> 5;
    const int wm = w >> 1, wn = w & 1;

    // loader lanes: 2 positions x 4 arrays, 16B each
    const int r0 = tid >> 2,          c0 = tid & 3;
    const int r1 = (tid + 256) >> 2,  c1 = tid & 3;   // same c, row+64
    const uint32_t so0 = smoff(r0, c0);
    const uint32_t so1 = smoff(r1, c1);

    auto load_stage = [&](int stage, int ch) {
        const uint32_t base = sb + stage * STG;
        const int k0 = ch * 32;
        const __nv_bfloat16* a0 = Ah + (size_t)(m0 + r0) * 1024 + k0 + c0 * 8;
        const __nv_bfloat16* a1 = Ah + (size_t)(m0 + r1) * 1024 + k0 + c1 * 8;
        const __nv_bfloat16* b0 = Al + (size_t)(m0 + r0) * 1024 + k0 + c0 * 8;
        const __nv_bfloat16* b1 = Al + (size_t)(m0 + r1) * 1024 + k0 + c1 * 8;
        const __nv_bfloat16* w0 = Wh + (size_t)(n0 + r0) * 1024 + k0 + c0 * 8;
        const __nv_bfloat16* w1 = Wh + (size_t)(n0 + r1) * 1024 + k0 + c1 * 8;
        const __nv_bfloat16* x0 = Wl + (size_t)(n0 + r0) * 1024 + k0 + c0 * 8;
        const __nv_bfloat16* x1 = Wl + (size_t)(n0 + r1) * 1024 + k0 + c1 * 8;
        cp16(base + so0, a0);                 cp16(base + so1, a1);
        cp16(base + OFF_AL + so0, b0);        cp16(base + OFF_AL + so1, b1);
        cp16(base + OFF_WH + so0, w0);        cp16(base + OFF_WH + so1, w1);
        cp16(base + OFF_WL + so0, x0);        cp16(base + OFF_WL + so1, x1);
    };

    float acc[2][8][4];
#pragma unroll
    for (int i = 0; i < 2; i++)
#pragma unroll
        for (int j = 0; j < 8; j++)
#pragma unroll
            for (int k = 0; k < 4; k++) acc[i][j][k] = 0.f;

    // ldmatrix lane addressing
    const int rA = wm * 32 + (lane & 15);                       // + mt*16
    const int cAbit = lane >> 4;                                // k-chunk bit
    const int rB = wn * 64 + (lane & 7) + ((lane & 16) >> 1);   // + g*16
    const int cBbit = (lane >> 3) & 1;

    load_stage(0, 0); CP_COMMIT();
    load_stage(1, 1); CP_COMMIT();

    for (int ch = 0; ch < 32; ch++) {
        CP_WAIT1();
        __syncthreads();
        const uint32_t base = sb + (ch & 1) * STG;

#pragma unroll
        for (int ks = 0; ks < 2; ks++) {
            uint32_t ah[2][4], al[2][4];
            const int cA = ks * 2 + cAbit;
            ldsm4(ah[0], base + smoff(rA, cA));
            ldsm4(ah[1], base + smoff(rA + 16, cA));
            ldsm4(al[0], base + OFF_AL + smoff(rA, cA));
            ldsm4(al[1], base + OFF_AL + smoff(rA + 16, cA));

            uint32_t bh[8][2], bl[8][2];
            const int cB = ks * 2 + cBbit;
#pragma unroll
            for (int g = 0; g < 4; g++) {
                uint32_t t[4];
                ldsm4(t, base + OFF_WH + smoff(rB + g * 16, cB));
                bh[2*g][0] = t[0]; bh[2*g][1] = t[1];
                bh[2*g+1][0] = t[2]; bh[2*g+1][1] = t[3];
                ldsm4(t, base + OFF_WL + smoff(rB + g * 16, cB));
                bl[2*g][0] = t[0]; bl[2*g][1] = t[1];
                bl[2*g+1][0] = t[2]; bl[2*g+1][1] = t[3];
            }
#pragma unroll
            for (int mt = 0; mt < 2; mt++)
#pragma unroll
                for (int nt = 0; nt < 8; nt++) {
                    mma16816(acc[mt][nt], ah[mt], bh[nt]);
                    mma16816(acc[mt][nt], ah[mt], bl[nt]);
                    mma16816(acc[mt][nt], al[mt], bh[nt]);
                }
        }
        __syncthreads();
        if (ch + 2 < 32) load_stage(ch & 1, ch + 2);
        CP_COMMIT();   // empty group when no load issued, keeps numbering
    }

    // Epilogue: acc[mt][nt][0..1] -> (m, n..n+1), [2..3] -> (m+8, n..n+1)
#pragma unroll
    for (int mt = 0; mt < 2; mt++) {
        const int mb = m0 + wm * 32 + mt * 16 + (lane >> 2);
#pragma unroll
        for (int nt = 0; nt < 8; nt++) {
            const int n = n0 + wn * 64 + nt * 8 + (lane & 3) * 2;
            const float b0v = bias[n], b1v = bias[n + 1];
#pragma unroll
            for (int pr = 0; pr < 2; pr++) {
                const int m = mb + pr * 8;
                float2 v;
                v.x = acc[mt][nt][pr * 2 + 0] + b0v;
                v.y = acc[mt][nt][pr * 2 + 1] + b1v;
                if (MODE == 0) {
                    const int b = m >> 11, t = m & 2047;
                    const int hh = n >> 6, dd = n & 63;
                    size_t o = (((size_t)(b * 16 + hh)) * 2048 + t) * 64 + dd;
                    *(float2*)(C + o) = v;
                } else {
                    size_t o = (size_t)m * 1024 + n;
                    float2 rr = *(const float2*)(resid + o);
                    v.x += rr.x; v.y += rr.y;
                    *(float2*)(C + o) = v;
                }
            }
        }
    }
}

// ---------------------------------------------------------------------------
// Flash attention (fp32 baseline, unchanged). Grid: (32 q-tiles, 32 b*h).
// ---------------------------------------------------------------------------
#define SCL 0.18033688011112042f   // (1/8) * log2(e)

__global__ __launch_bounds__(256) void attn_kernel()
{
    __shared__ float Qt[64 * 64];
    __shared__ float KP[64 * 64];
    __shared__ float Vs[64 * 64];

    const int bh = blockIdx.y;
    const int q0 = blockIdx.x * 64;
    const float* Qg = g_Q + ((size_t)bh * 2048 + q0) * 64;
    const float* Kb = g_K + (size_t)bh * 2048 * 64;
    const float* Vb = g_V + (size_t)bh * 2048 * 64;

    const int tid = threadIdx.x;
    const int tx = tid & 15, ty = tid >> 4;
    const int tx4 = tx * 4, ty4 = ty * 4;

#pragma unroll
    for (int i = 0; i < 4; i++) {
        int idx = tid + i * 256;
        int r  = idx >> 4;
        int d0 = (idx & 15) << 2;
        float4 v = *(const float4*)(Qg + r * 64 + d0);
        int col = r ^ d0;
        Qt[(d0 + 0) * 64 + col] = v.x * SCL;
        Qt[(d0 + 1) * 64 + col] = v.y * SCL;
        Qt[(d0 + 2) * 64 + col] = v.z * SCL;
        Qt[(d0 + 3) * 64 + col] = v.w * SCL;
    }

    float m_run[4] = {-1e30f, -1e30f, -1e30f, -1e30f};
    float l_run[4] = {0.f, 0.f, 0.f, 0.f};
    float acc[4][4];
#pragma unroll
    for (int i = 0; i < 4; i++)
#pragma unroll
        for (int j = 0; j < 4; j++) acc[i][j] = 0.f;

    for (int t = 0; t < 32; t++) {
        __syncthreads();
        const float* Kg = Kb + (size_t)t * 64 * 64;
        const float* Vg = Vb + (size_t)t * 64 * 64;
#pragma unroll
        for (int i = 0; i < 4; i++) {
            int idx = tid + i * 256;
            int r  = idx >> 4;
            int d0 = (idx & 15) << 2;
            float4 kv = *(const float4*)(Kg + r * 64 + d0);
            int col = r ^ d0;
            KP[(d0 + 0) * 64 + col] = kv.x;
            KP[(d0 + 1) * 64 + col] = kv.y;
            KP[(d0 + 2) * 64 + col] = kv.z;
            KP[(d0 + 3) * 64 + col] = kv.w;
            float4 vv = *(const float4*)(Vg + r * 64 + d0);
            *(float4*)(&Vs[r * 64 + d0]) = vv;
        }
        __syncthreads();

        float s[4][4];
#pragma unroll
        for (int i = 0; i < 4; i++)
#pragma unroll
            for (int j = 0; j < 4; j++) s[i][j] = 0.f;

#pragma unroll 8
        for (int d = 0; d < 64; d++) {
            int base = d * 64;
            int cst  = d & 60;
            float4 k4 = *(const float4*)(&KP[base + (tx4 ^ cst)]);
            float q0v = Qt[base + ((ty4 + 0) ^ cst)];
            float q1v = Qt[base + ((ty4 + 1) ^ cst)];
            float q2v = Qt[base + ((ty4 + 2) ^ cst)];
            float q3v = Qt[base + ((ty4 + 3) ^ cst)];
            s[0][0] = fmaf(q0v, k4.x, s[0][0]); s[0][1] = fmaf(q0v, k4.y, s[0][1]);
            s[0][2] = fmaf(q0v, k4.z, s[0][2]); s[0][3] = fmaf(q0v, k4.w, s[0][3]);
            s[1][0] = fmaf(q1v, k4.x, s[1][0]); s[1][1] = fmaf(q1v, k4.y, s[1][1]);
            s[1][2] = fmaf(q1v, k4.z, s[1][2]); s[1][3] = fmaf(q1v, k4.w, s[1][3]);
            s[2][0] = fmaf(q2v, k4.x, s[2][0]); s[2][1] = fmaf(q2v, k4.y, s[2][1]);
            s[2][2] = fmaf(q2v, k4.z, s[2][2]); s[2][3] = fmaf(q2v, k4.w, s[2][3]);
            s[3][0] = fmaf(q3v, k4.x, s[3][0]); s[3][1] = fmaf(q3v, k4.y, s[3][1]);
            s[3][2] = fmaf(q3v, k4.z, s[3][2]); s[3][3] = fmaf(q3v, k4.w, s[3][3]);
        }

        float p[4][4];
#pragma unroll
        for (int i = 0; i < 4; i++) {
            float rm = fmaxf(fmaxf(s[i][0], s[i][1]), fmaxf(s[i][2], s[i][3]));
            rm = fmaxf(rm, __shfl_xor_sync(0xffffffffu, rm, 1));
            rm = fmaxf(rm, __shfl_xor_sync(0xffffffffu, rm, 2));
            rm = fmaxf(rm, __shfl_xor_sync(0xffffffffu, rm, 4));
            rm = fmaxf(rm, __shfl_xor_sync(0xffffffffu, rm, 8));
            float mnew  = fmaxf(m_run[i], rm);
            float alpha = ex2f(m_run[i] - mnew);
            m_run[i] = mnew;
            p[i][0] = ex2f(s[i][0] - mnew);
            p[i][1] = ex2f(s[i][1] - mnew);
            p[i][2] = ex2f(s[i][2] - mnew);
            p[i][3] = ex2f(s[i][3] - mnew);
            float rs = p[i][0] + p[i][1] + p[i][2] + p[i][3];
            rs += __shfl_xor_sync(0xffffffffu, rs, 1);
            rs += __shfl_xor_sync(0xffffffffu, rs, 2);
            rs += __shfl_xor_sync(0xffffffffu, rs, 4);
            rs += __shfl_xor_sync(0xffffffffu, rs, 8);
            l_run[i] = l_run[i] * alpha + rs;
            acc[i][0] *= alpha; acc[i][1] *= alpha;
            acc[i][2] *= alpha; acc[i][3] *= alpha;
        }

        __syncthreads();
#pragma unroll
        for (int i = 0; i < 4; i++)
            *(float4*)(&KP[(ty4 + i) * 64 + tx4]) =
                make_float4(p[i][0], p[i][1], p[i][2], p[i][3]);
        __syncthreads();

#pragma unroll 8
        for (int c = 0; c < 64; c++) {
            float4 v4 = *(const float4*)(&Vs[c * 64 + tx4]);
            float p0 = KP[(ty4 + 0) * 64 + c];
            float p1 = KP[(ty4 + 1) * 64 + c];
            float p2 = KP[(ty4 + 2) * 64 + c];
            float p3 = KP[(ty4 + 3) * 64 + c];
            acc[0][0] = fmaf(p0, v4.x, acc[0][0]); acc[0][1] = fmaf(p0, v4.y, acc[0][1]);
            acc[0][2] = fmaf(p0, v4.z, acc[0][2]); acc[0][3] = fmaf(p0, v4.w, acc[0][3]);
            acc[1][0] = fmaf(p1, v4.x, acc[1][0]); acc[1][1] = fmaf(p1, v4.y, acc[1][1]);
            acc[1][2] = fmaf(p1, v4.z, acc[1][2]); acc[1][3] = fmaf(p1, v4.w, acc[1][3]);
            acc[2][0] = fmaf(p2, v4.x, acc[2][0]); acc[2][1] = fmaf(p2, v4.y, acc[2][1]);
            acc[2][2] = fmaf(p2, v4.z, acc[2][2]); acc[2][3] = fmaf(p2, v4.w, acc[2][3]);
            acc[3][0] = fmaf(p3, v4.x, acc[3][0]); acc[3][1] = fmaf(p3, v4.y, acc[3][1]);
            acc[3][2] = fmaf(p3, v4.z, acc[3][2]); acc[3][3] = fmaf(p3, v4.w, acc[3][3]);
        }
    }

    const int b = bh >> 4, hh = bh & 15;
#pragma unroll
    for (int i = 0; i < 4; i++) {
        float inv = 1.0f / l_run[i];
        size_t o = ((size_t)(b * 2048 + q0 + ty4 + i)) * 1024 + hh * 64 + tx4;
        *(float4*)(&g_ctx[o]) = make_float4(acc[i][0] * inv, acc[i][1] * inv,
                                            acc[i][2] * inv, acc[i][3] * inv);
    }
}

// ---------------------------------------------------------------------------
// LayerNorm over rows of 1024. One block per row, 256 threads x float4.
// ---------------------------------------------------------------------------
__global__ __launch_bounds__(256) void ln_kernel(
    const float* __restrict__ x, const float* __restrict__ gamma,
    const float* __restrict__ beta, float* __restrict__ out)
{
    __shared__ float rs[8], rq[8];
    __shared__ float s_mu, s_rstd;
    const int row = blockIdx.x;
    const int tid = threadIdx.x;
    const float* xr = x + (size_t)row * 1024;

    float4 v = *(const float4*)(xr + tid * 4);
    float s = v.x + v.y + v.z + v.w;
    float q = v.x * v.x + v.y * v.y + v.z * v.z + v.w * v.w;
#pragma unroll
    for (int o = 16; o > 0; o >>= 1) {
        s += __shfl_xor_sync(0xffffffffu, s, o);
        q += __shfl_xor_sync(0xffffffffu, q, o);
    }
    if ((tid & 31) == 0) { rs[tid >> 5] = s; rq[tid >> 5] = q; }
    __syncthreads();
    if (tid == 0) {
        float S = 0.f, Q = 0.f;
#pragma unroll
        for (int w = 0; w < 8; w++) { S += rs[w]; Q += rq[w]; }
        float mu  = S * (1.0f / 1024.0f);
        float var = Q * (1.0f / 1024.0f) - mu * mu;
        s_mu   = mu;
        s_rstd = rsqrtf(var + 1e-6f);
    }
    __syncthreads();
    float mu = s_mu, r = s_rstd;
    float4 g  = *(const float4*)(gamma + tid * 4);
    float4 bb = *(const float4*)(beta + tid * 4);
    float4 o4;
    o4.x = (v.x - mu) * r * g.x + bb.x;
    o4.y = (v.y - mu) * r * g.y + bb.y;
    o4.z = (v.z - mu) * r * g.z + bb.z;
    o4.w = (v.w - mu) * r * g.w + bb.w;
    *(float4*)(out + (size_t)row * 1024 + tid * 4) = o4;
}

// ---------------------------------------------------------------------------
// Launch sequence
// ---------------------------------------------------------------------------
extern "C" void kernel_launch(void* const* d_in, const int* in_sizes, int n_in,
                              void* d_out, int out_size)
{
    (void)in_sizes; (void)n_in; (void)out_size;
    const float* h     = (const float*)d_in[0];
    const float* Wq    = (const float*)d_in[1];
    const float* bq    = (const float*)d_in[2];
    const float* Wk    = (const float*)d_in[3];
    const float* bk    = (const float*)d_in[4];
    const float* Wv    = (const float*)d_in[5];
    const float* bv    = (const float*)d_in[6];
    const float* Wo    = (const float*)d_in[7];
    const float* bo    = (const float*)d_in[8];
    const float* gamma = (const float*)d_in[9];
    const float* beta  = (const float*)d_in[10];
    float* out = (float*)d_out;

    float *qp, *kp, *vp, *cp, *tp;
    cudaGetSymbolAddress((void**)&qp, g_Q);
    cudaGetSymbolAddress((void**)&kp, g_K);
    cudaGetSymbolAddress((void**)&vp, g_V);
    cudaGetSymbolAddress((void**)&cp, g_ctx);
    cudaGetSymbolAddress((void**)&tp, g_tmp);

    __nv_bfloat16 *hh, *hl, *ch, *cl;
    __nv_bfloat16 *wqh, *wql, *wkh, *wkl, *wvh, *wvl, *woh, *wol;
    cudaGetSymbolAddress((void**)&hh,  g_hh);  cudaGetSymbolAddress((void**)&hl,  g_hl);
    cudaGetSymbolAddress((void**)&ch,  g_ch);  cudaGetSymbolAddress((void**)&cl,  g_cl);
    cudaGetSymbolAddress((void**)&wqh, g_wqh); cudaGetSymbolAddress((void**)&wql, g_wql);
    cudaGetSymbolAddress((void**)&wkh, g_wkh); cudaGetSymbolAddress((void**)&wkl, g_wkl);
    cudaGetSymbolAddress((void**)&wvh, g_wvh); cudaGetSymbolAddress((void**)&wvl, g_wvl);
    cudaGetSymbolAddress((void**)&woh, g_woh); cudaGetSymbolAddress((void**)&wol, g_wol);

    cudaFuncSetAttribute(gemm_mma<0>, cudaFuncAttributeMaxDynamicSharedMemorySize, GEMM_SMEM);
    cudaFuncSetAttribute(gemm_mma<1>, cudaFuncAttributeMaxDynamicSharedMemorySize, GEMM_SMEM);

    // Split inputs into bf16 hi/lo
    split8<<<ROW_ELEMS / 2048, 256>>>(h,  hh,  hl);
    split8<<<W_ELEMS  / 2048, 256>>>(Wq, wqh, wql);
    split8<<<W_ELEMS  / 2048, 256>>>(Wk, wkh, wkl);
    split8<<<W_ELEMS  / 2048, 256>>>(Wv, wvh, wvl);
    split8<<<W_ELEMS  / 2048, 256>>>(Wo, woh, wol);

    dim3 gg(1024 / 128, 4096 / 128);  // (8, 32)
    gemm_mma<0><<<gg, 256, GEMM_SMEM>>>(hh, hl, wqh, wql, bq, nullptr, qp);
    gemm_mma<0><<<gg, 256, GEMM_SMEM>>>(hh, hl, wkh, wkl, bk, nullptr, kp);
    gemm_mma<0><<<gg, 256, GEMM_SMEM>>>(hh, hl, wvh, wvl, bv, nullptr, vp);

    attn_kernel<<<dim3(32, 32), 256>>>();

    split8<<<ROW_ELEMS / 2048, 256>>>(cp, ch, cl);
    gemm_mma<1><<<gg, 256, GEMM_SMEM>>>(ch, cl, woh, wol, bo, h, tp);

    ln_kernel<<<4096, 256>>>(tp, gamma, beta, out);
}

// round 4
// speedup vs baseline: 3.2615x; 2.2282x over previous
#include <cuda_runtime.h>
#include <cuda_bf16.h>
#include <cstdint>

// ---------------------------------------------------------------------------
// MHA block on GB300 (sm_103 baseline PTX): mma.sync bf16 3-term split for
// QKV/O projections AND flash attention. fp32-accurate. Fused LayerNorm.
// B=2, T=2048, H=1024, 16 heads x 64 dim.
// ---------------------------------------------------------------------------

#define QKV_ELEMS (2*16*2048*64)   // 4,194,304
#define ROW_ELEMS (4096*1024)      // 4,194,304
#define W_ELEMS   (1024*1024)

__device__ float g_tmp[ROW_ELEMS];

// bf16 hi/lo split arrays
__device__ __nv_bfloat16 g_hh[ROW_ELEMS],  g_hl[ROW_ELEMS];    // h
__device__ __nv_bfloat16 g_ch[ROW_ELEMS],  g_cl[ROW_ELEMS];    // ctx (from attn)
__device__ __nv_bfloat16 g_Qh[QKV_ELEMS],  g_Ql[QKV_ELEMS];    // scaled Q
__device__ __nv_bfloat16 g_Kh[QKV_ELEMS],  g_Kl[QKV_ELEMS];
__device__ __nv_bfloat16 g_Vh[QKV_ELEMS],  g_Vl[QKV_ELEMS];
__device__ __nv_bfloat16 g_wqh[W_ELEMS],   g_wql[W_ELEMS];
__device__ __nv_bfloat16 g_wkh[W_ELEMS],   g_wkl[W_ELEMS];
__device__ __nv_bfloat16 g_wvh[W_ELEMS],   g_wvl[W_ELEMS];
__device__ __nv_bfloat16 g_woh[W_ELEMS],   g_wol[W_ELEMS];

#define SCL 0.18033688011112042f   // (1/8) * log2(e)

__device__ __forceinline__ float ex2f(float x) {
    float y;
    asm("ex2.approx.ftz.f32 %0, %1;" : "=f"(y) : "f"(x));
    return y;
}
__device__ __forceinline__ uint32_t smem_u32(const void* p) {
    uint32_t a;
    asm("{ .reg .u64 t; cvta.to.shared.u64 t, %1; cvt.u32.u64 %0, t; }"
        : "=r"(a) : "l"(p));
    return a;
}
__device__ __forceinline__ void cp16(uint32_t saddr, const void* g) {
    asm volatile("cp.async.cg.shared.global [%0], [%1], 16;"
                 :: "r"(saddr), "l"(g) : "memory");
}
#define CP_COMMIT() asm volatile("cp.async.commit_group;" ::: "memory")
#define CP_WAIT1()  asm volatile("cp.async.wait_group 1;" ::: "memory")

__device__ __forceinline__ void ldsm4(uint32_t* r, uint32_t addr) {
    asm volatile("ldmatrix.sync.aligned.m8n8.x4.shared.b16 {%0,%1,%2,%3}, [%4];"
                 : "=r"(r[0]), "=r"(r[1]), "=r"(r[2]), "=r"(r[3]) : "r"(addr));
}
__device__ __forceinline__ void ldsm4t(uint32_t* r, uint32_t addr) {
    asm volatile("ldmatrix.sync.aligned.m8n8.x4.trans.shared.b16 {%0,%1,%2,%3}, [%4];"
                 : "=r"(r[0]), "=r"(r[1]), "=r"(r[2]), "=r"(r[3]) : "r"(addr));
}
__device__ __forceinline__ void mma16816(float* d, const uint32_t* a, const uint32_t* b) {
    asm volatile(
        "mma.sync.aligned.m16n8k16.row.col.f32.bf16.bf16.f32 "
        "{%0,%1,%2,%3}, {%4,%5,%6,%7}, {%8,%9}, {%0,%1,%2,%3};"
        : "+f"(d[0]), "+f"(d[1]), "+f"(d[2]), "+f"(d[3])
        : "r"(a[0]), "r"(a[1]), "r"(a[2]), "r"(a[3]), "r"(b[0]), "r"(b[1]));
}
// pack (lo elem, hi elem) -> bf16x2
__device__ __forceinline__ uint32_t packbf2(float lo, float hi) {
    uint32_t r;
    asm("cvt.rn.bf16x2.f32 %0, %1, %2;" : "=r"(r) : "f"(hi), "f"(lo));
    return r;
}
__device__ __forceinline__ float bflo(uint32_t p) { return __uint_as_float(p << 16); }
__device__ __forceinline__ float bfhi(uint32_t p) { return __uint_as_float(p & 0xffff0000u); }

// ---------------------------------------------------------------------------
// bf16 split pre-pass: hi = bf16(x), lo = bf16(x - hi).
// ---------------------------------------------------------------------------
__global__ __launch_bounds__(256) void split8(
    const float* __restrict__ x, __nv_bfloat16* __restrict__ hi,
    __nv_bfloat16* __restrict__ lo)
{
    int i = (blockIdx.x * 256 + threadIdx.x) * 8;
    float4 v0 = *(const float4*)(x + i);
    float4 v1 = *(const float4*)(x + i + 4);
    uint4 ph, pl;
    ph.x = packbf2(v0.x, v0.y); ph.y = packbf2(v0.z, v0.w);
    ph.z = packbf2(v1.x, v1.y); ph.w = packbf2(v1.z, v1.w);
    pl.x = packbf2(v0.x - bflo(ph.x), v0.y - bfhi(ph.x));
    pl.y = packbf2(v0.z - bflo(ph.y), v0.w - bfhi(ph.y));
    pl.z = packbf2(v1.x - bflo(ph.z), v1.y - bfhi(ph.z));
    pl.w = packbf2(v1.z - bflo(ph.w), v1.w - bfhi(ph.w));
    *(uint4*)(hi + i) = ph;
    *(uint4*)(lo + i) = pl;
}

// ---------------------------------------------------------------------------
// mma.sync NT GEMM: C[M,N] = A[M,K] @ W[N,K]^T + bias[N], K = 1024.
// 3-term bf16 split. Block 128x128x32, 256 threads, 2-stage cp.async.
// MODE 0: Q -> scale by SCL, split, write hi/lo to [b,h,t,d]
// MODE 1: K/V -> split, write hi/lo to [b,h,t,d]
// MODE 2: O-proj -> fp32 + residual, row-major
// ---------------------------------------------------------------------------
#define STG 32768
#define OFF_AL 8192
#define OFF_WH 16384
#define OFF_WL 24576
#define GEMM_SMEM (2 * STG)

__device__ __forceinline__ uint32_t smoff(int row, int c) {
    return row * 64 + ((c ^ ((row >> 1) & 3)) << 4);
}

template<int MODE>
__global__ __launch_bounds__(256)
void gemm_mma(const __nv_bfloat16* __restrict__ Ah, const __nv_bfloat16* __restrict__ Al,
              const __nv_bfloat16* __restrict__ Wh, const __nv_bfloat16* __restrict__ Wl,
              const float* __restrict__ bias, const float* __restrict__ resid,
              float* __restrict__ C,
              __nv_bfloat16* __restrict__ Dh, __nv_bfloat16* __restrict__ Dl)
{
    extern __shared__ char smem[];
    const uint32_t sb = smem_u32(smem);
    const int tid = threadIdx.x;
    const int n0 = blockIdx.x * 128;
    const int m0 = blockIdx.y * 128;
    const int lane = tid & 31, w = tid >> 5;
    const int wm = w >> 1, wn = w & 1;

    const int r0 = tid >> 2,          c0 = tid & 3;
    const int r1 = (tid + 256) >> 2,  c1 = tid & 3;
    const uint32_t so0 = smoff(r0, c0);
    const uint32_t so1 = smoff(r1, c1);

    auto load_stage = [&](int stage, int ch) {
        const uint32_t base = sb + stage * STG;
        const int k0 = ch * 32;
        cp16(base + so0,          Ah + (size_t)(m0 + r0) * 1024 + k0 + c0 * 8);
        cp16(base + so1,          Ah + (size_t)(m0 + r1) * 1024 + k0 + c1 * 8);
        cp16(base + OFF_AL + so0, Al + (size_t)(m0 + r0) * 1024 + k0 + c0 * 8);
        cp16(base + OFF_AL + so1, Al + (size_t)(m0 + r1) * 1024 + k0 + c1 * 8);
        cp16(base + OFF_WH + so0, Wh + (size_t)(n0 + r0) * 1024 + k0 + c0 * 8);
        cp16(base + OFF_WH + so1, Wh + (size_t)(n0 + r1) * 1024 + k0 + c1 * 8);
        cp16(base + OFF_WL + so0, Wl + (size_t)(n0 + r0) * 1024 + k0 + c0 * 8);
        cp16(base + OFF_WL + so1, Wl + (size_t)(n0 + r1) * 1024 + k0 + c1 * 8);
    };

    float acc[2][8][4];
#pragma unroll
    for (int i = 0; i < 2; i++)
#pragma unroll
        for (int j = 0; j < 8; j++)
#pragma unroll
            for (int k = 0; k < 4; k++) acc[i][j][k] = 0.f;

    const int rA = wm * 32 + (lane & 15);
    const int cAbit = lane >> 4;
    const int rB = wn * 64 + (lane & 7) + ((lane & 16) >> 1);
    const int cBbit = (lane >> 3) & 1;

    load_stage(0, 0); CP_COMMIT();
    load_stage(1, 1); CP_COMMIT();

    for (int ch = 0; ch < 32; ch++) {
        CP_WAIT1();
        __syncthreads();
        const uint32_t base = sb + (ch & 1) * STG;

#pragma unroll
        for (int ks = 0; ks < 2; ks++) {
            uint32_t ah[2][4], al[2][4];
            const int cA = ks * 2 + cAbit;
            ldsm4(ah[0], base + smoff(rA, cA));
            ldsm4(ah[1], base + smoff(rA + 16, cA));
            ldsm4(al[0], base + OFF_AL + smoff(rA, cA));
            ldsm4(al[1], base + OFF_AL + smoff(rA + 16, cA));

            uint32_t bh[8][2], bl[8][2];
            const int cB = ks * 2 + cBbit;
#pragma unroll
            for (int g = 0; g < 4; g++) {
                uint32_t t[4];
                ldsm4(t, base + OFF_WH + smoff(rB + g * 16, cB));
                bh[2*g][0] = t[0]; bh[2*g][1] = t[1];
                bh[2*g+1][0] = t[2]; bh[2*g+1][1] = t[3];
                ldsm4(t, base + OFF_WL + smoff(rB + g * 16, cB));
                bl[2*g][0] = t[0]; bl[2*g][1] = t[1];
                bl[2*g+1][0] = t[2]; bl[2*g+1][1] = t[3];
            }
#pragma unroll
            for (int mt = 0; mt < 2; mt++)
#pragma unroll
                for (int nt = 0; nt < 8; nt++) {
                    mma16816(acc[mt][nt], ah[mt], bh[nt]);
                    mma16816(acc[mt][nt], ah[mt], bl[nt]);
                    mma16816(acc[mt][nt], al[mt], bh[nt]);
                }
        }
        __syncthreads();
        if (ch + 2 < 32) load_stage(ch & 1, ch + 2);
        CP_COMMIT();
    }

#pragma unroll
    for (int mt = 0; mt < 2; mt++) {
        const int mb = m0 + wm * 32 + mt * 16 + (lane >> 2);
#pragma unroll
        for (int nt = 0; nt < 8; nt++) {
            const int n = n0 + wn * 64 + nt * 8 + (lane & 3) * 2;
            const float b0v = bias[n], b1v = bias[n + 1];
#pragma unroll
            for (int pr = 0; pr < 2; pr++) {
                const int m = mb + pr * 8;
                float vx = acc[mt][nt][pr * 2 + 0] + b0v;
                float vy = acc[mt][nt][pr * 2 + 1] + b1v;
                if (MODE == 2) {
                    size_t o = (size_t)m * 1024 + n;
                    float2 rr = *(const float2*)(resid + o);
                    float2 v; v.x = vx + rr.x; v.y = vy + rr.y;
                    *(float2*)(C + o) = v;
                } else {
                    if (MODE == 0) { vx *= SCL; vy *= SCL; }
                    const int b = m >> 11, t = m & 2047;
                    const int hh = n >> 6, dd = n & 63;
                    size_t o = (((size_t)(b * 16 + hh)) * 2048 + t) * 64 + dd;
                    uint32_t hp = packbf2(vx, vy);
                    uint32_t lp = packbf2(vx - bflo(hp), vy - bfhi(hp));
                    *(uint32_t*)((__nv_bfloat16*)Dh + o) = hp;
                    *(uint32_t*)((__nv_bfloat16*)Dl + o) = lp;
                }
            }
        }
    }
}

// ---------------------------------------------------------------------------
// Flash attention on tensor pipe. Grid (16 q-tiles, 32 b*h), 256 thr (8 warps).
// q-tile 128 (warp = 16 rows, full n=64), kv-tile 64, 32 iters.
// 3-term bf16 split for S = QK^T and O += PV. Online softmax in log2 domain.
// Smem: Q hi/lo 32KB + 2-stage K/V hi/lo 64KB = 96KB.
// ---------------------------------------------------------------------------
#define AQ_HI 0
#define AQ_LO 16384
#define ASTG(s) (32768 + (s) * 32768)
#define AKH 0
#define AKL 8192
#define AVH 16384
#define AVL 24576
#define ATT_SMEM 98304

__device__ __forceinline__ uint32_t aoff(int row, int c) {
    return row * 128 + ((c ^ (row & 7)) << 4);
}

__global__ __launch_bounds__(256)
void attn_mma(const __nv_bfloat16* __restrict__ Qh, const __nv_bfloat16* __restrict__ Ql,
              const __nv_bfloat16* __restrict__ Kh, const __nv_bfloat16* __restrict__ Kl,
              const __nv_bfloat16* __restrict__ Vh, const __nv_bfloat16* __restrict__ Vl,
              __nv_bfloat16* __restrict__ Ch, __nv_bfloat16* __restrict__ Cl)
{
    extern __shared__ char smem[];
    const uint32_t sb = smem_u32(smem);
    const int tid = threadIdx.x;
    const int lane = tid & 31, w = tid >> 5;
    const int bh = blockIdx.y;
    const int q0 = blockIdx.x * 128;
    const size_t qbase  = ((size_t)bh * 2048 + q0) * 64;
    const size_t kvbase = (size_t)bh * 2048 * 64;

    // Q tile loader: 128 rows x 8 chunks, 4 passes
#pragma unroll
    for (int p = 0; p < 4; p++) {
        int idx = tid + p * 256;
        int row = idx >> 3, c = idx & 7;
        size_t go = qbase + (size_t)row * 64 + c * 8;
        cp16(sb + AQ_HI + aoff(row, c), Qh + go);
        cp16(sb + AQ_LO + aoff(row, c), Ql + go);
    }
    // K/V stage loader
    auto load_kv = [&](int s, int t) {
        const uint32_t base = sb + ASTG(s);
        const size_t kvo = kvbase + (size_t)t * 64 * 64;
#pragma unroll
        for (int p = 0; p < 2; p++) {
            int idx = tid + p * 256;
            int row = idx >> 3, c = idx & 7;
            size_t go = kvo + (size_t)row * 64 + c * 8;
            uint32_t so = aoff(row, c);
            cp16(base + AKH + so, Kh + go);
            cp16(base + AKL + so, Kl + go);
            cp16(base + AVH + so, Vh + go);
            cp16(base + AVL + so, Vl + go);
        }
    };

    load_kv(0, 0); CP_COMMIT();
    load_kv(1, 1); CP_COMMIT();
    CP_WAIT1();
    __syncthreads();

    // Q fragments (persistent): warp rows w*16..w*16+15
    const int rA = w * 16 + (lane & 15);
    const int cAbit = lane >> 4;
    uint32_t qh[4][4], ql[4][4];
#pragma unroll
    for (int kc = 0; kc < 4; kc++) {
        ldsm4(qh[kc], sb + AQ_HI + aoff(rA, kc * 2 + cAbit));
        ldsm4(ql[kc], sb + AQ_LO + aoff(rA, kc * 2 + cAbit));
    }

    const int rBb = (lane & 7) + ((lane & 16) >> 1);  // + g*16
    const int cBbit = (lane >> 3) & 1;
    const int rVb = lane & 15;                        // + kc*16
    const int cVbit = lane >> 4;                      // + g*2

    float m0r = -1e30f, m1r = -1e30f, l0r = 0.f, l1r = 0.f;
    float acc[8][4];
#pragma unroll
    for (int i = 0; i < 8; i++)
#pragma unroll
        for (int j = 0; j < 4; j++) acc[i][j] = 0.f;

    for (int t = 0; t < 32; t++) {
        if (t > 0) { CP_WAIT1(); __syncthreads(); }
        const uint32_t base = sb + ASTG(t & 1);

        // ---- S = Q @ K^T (3-term) ----
        float sa[8][4];
#pragma unroll
        for (int i = 0; i < 8; i++)
#pragma unroll
            for (int j = 0; j < 4; j++) sa[i][j] = 0.f;

#pragma unroll
        for (int kc = 0; kc < 4; kc++) {
            const int cB = kc * 2 + cBbit;
            uint32_t bh_[8][2], bl_[8][2];
#pragma unroll
            for (int g = 0; g < 4; g++) {
                uint32_t tp[4];
                ldsm4(tp, base + AKH + aoff(rBb + g * 16, cB));
                bh_[2*g][0] = tp[0]; bh_[2*g][1] = tp[1];
                bh_[2*g+1][0] = tp[2]; bh_[2*g+1][1] = tp[3];
                ldsm4(tp, base + AKL + aoff(rBb + g * 16, cB));
                bl_[2*g][0] = tp[0]; bl_[2*g][1] = tp[1];
                bl_[2*g+1][0] = tp[2]; bl_[2*g+1][1] = tp[3];
            }
#pragma unroll
            for (int nt = 0; nt < 8; nt++) {
                mma16816(sa[nt], qh[kc], bh_[nt]);
                mma16816(sa[nt], qh[kc], bl_[nt]);
                mma16816(sa[nt], ql[kc], bh_[nt]);
            }
        }

        // ---- online softmax (rows lane>>2 and +8) ----
        float rm0 = -1e30f, rm1 = -1e30f;
#pragma unroll
        for (int nt = 0; nt < 8; nt++) {
            rm0 = fmaxf(rm0, fmaxf(sa[nt][0], sa[nt][1]));
            rm1 = fmaxf(rm1, fmaxf(sa[nt][2], sa[nt][3]));
        }
        rm0 = fmaxf(rm0, __shfl_xor_sync(0xffffffffu, rm0, 1));
        rm0 = fmaxf(rm0, __shfl_xor_sync(0xffffffffu, rm0, 2));
        rm1 = fmaxf(rm1, __shfl_xor_sync(0xffffffffu, rm1, 1));
        rm1 = fmaxf(rm1, __shfl_xor_sync(0xffffffffu, rm1, 2));
        const float mn0 = fmaxf(m0r, rm0), mn1 = fmaxf(m1r, rm1);
        const float a0 = ex2f(m0r - mn0),  a1 = ex2f(m1r - mn1);
        m0r = mn0; m1r = mn1;

        float rs0 = 0.f, rs1 = 0.f;
#pragma unroll
        for (int nt = 0; nt < 8; nt++) {
            sa[nt][0] = ex2f(sa[nt][0] - mn0);
            sa[nt][1] = ex2f(sa[nt][1] - mn0);
            sa[nt][2] = ex2f(sa[nt][2] - mn1);
            sa[nt][3] = ex2f(sa[nt][3] - mn1);
            rs0 += sa[nt][0] + sa[nt][1];
            rs1 += sa[nt][2] + sa[nt][3];
        }
        rs0 += __shfl_xor_sync(0xffffffffu, rs0, 1);
        rs0 += __shfl_xor_sync(0xffffffffu, rs0, 2);
        rs1 += __shfl_xor_sync(0xffffffffu, rs1, 1);
        rs1 += __shfl_xor_sync(0xffffffffu, rs1, 2);
        l0r = l0r * a0 + rs0;
        l1r = l1r * a1 + rs1;
#pragma unroll
        for (int nt = 0; nt < 8; nt++) {
            acc[nt][0] *= a0; acc[nt][1] *= a0;
            acc[nt][2] *= a1; acc[nt][3] *= a1;
        }

        // ---- P fragments: hi + lo split, acc-layout == A-layout ----
        uint32_t ph[4][4], pl[4][4];
#pragma unroll
        for (int kc = 0; kc < 4; kc++) {
            const int t0 = 2 * kc, t1 = 2 * kc + 1;
            ph[kc][0] = packbf2(sa[t0][0], sa[t0][1]);
            ph[kc][1] = packbf2(sa[t0][2], sa[t0][3]);
            ph[kc][2] = packbf2(sa[t1][0], sa[t1][1]);
            ph[kc][3] = packbf2(sa[t1][2], sa[t1][3]);
            pl[kc][0] = packbf2(sa[t0][0] - bflo(ph[kc][0]), sa[t0][1] - bfhi(ph[kc][0]));
            pl[kc][1] = packbf2(sa[t0][2] - bflo(ph[kc][1]), sa[t0][3] - bfhi(ph[kc][1]));
            pl[kc][2] = packbf2(sa[t1][0] - bflo(ph[kc][2]), sa[t1][1] - bfhi(ph[kc][2]));
            pl[kc][3] = packbf2(sa[t1][2] - bflo(ph[kc][3]), sa[t1][3] - bfhi(ph[kc][3]));
        }

        // ---- O += P @ V (3-term), V via ldmatrix.trans ----
#pragma unroll
        for (int kc = 0; kc < 4; kc++) {
            const int rV = kc * 16 + rVb;
#pragma unroll
            for (int g = 0; g < 4; g++) {
                const int cV = g * 2 + cVbit;
                uint32_t tv[4], tl[4];
                ldsm4t(tv, base + AVH + aoff(rV, cV));
                ldsm4t(tl, base + AVL + aoff(rV, cV));
                mma16816(acc[2*g],   ph[kc], tv);
                mma16816(acc[2*g],   ph[kc], tl);
                mma16816(acc[2*g],   pl[kc], tv);
                mma16816(acc[2*g+1], ph[kc], tv + 2);
                mma16816(acc[2*g+1], ph[kc], tl + 2);
                mma16816(acc[2*g+1], pl[kc], tv + 2);
            }
        }

        __syncthreads();
        if (t + 2 < 32) load_kv(t & 1, t + 2);
        CP_COMMIT();
    }

    // ---- epilogue: ctx hi/lo bf16 at [b*T + q][head*64 + d] ----
    const float inv0 = 1.0f / l0r, inv1 = 1.0f / l1r;
    const int b_ = bh >> 4, hh_ = bh & 15;
    const int row0 = b_ * 2048 + q0 + w * 16 + (lane >> 2);
#pragma unroll
    for (int pr = 0; pr < 2; pr++) {
        const int row = row0 + pr * 8;
        const float inv = pr ? inv1 : inv0;
#pragma unroll
        for (int nt = 0; nt < 8; nt++) {
            const int col = hh_ * 64 + nt * 8 + (lane & 3) * 2;
            float vx = acc[nt][pr * 2 + 0] * inv;
            float vy = acc[nt][pr * 2 + 1] * inv;
            uint32_t hp = packbf2(vx, vy);
            uint32_t lp = packbf2(vx - bflo(hp), vy - bfhi(hp));
            size_t o = (size_t)row * 1024 + col;
            *(uint32_t*)(Ch + o) = hp;
            *(uint32_t*)(Cl + o) = lp;
        }
    }
}

// ---------------------------------------------------------------------------
// LayerNorm over rows of 1024.
// ---------------------------------------------------------------------------
__global__ __launch_bounds__(256) void ln_kernel(
    const float* __restrict__ x, const float* __restrict__ gamma,
    const float* __restrict__ beta, float* __restrict__ out)
{
    __shared__ float rs[8], rq[8];
    __shared__ float s_mu, s_rstd;
    const int row = blockIdx.x;
    const int tid = threadIdx.x;
    const float* xr = x + (size_t)row * 1024;

    float4 v = *(const float4*)(xr + tid * 4);
    float s = v.x + v.y + v.z + v.w;
    float q = v.x * v.x + v.y * v.y + v.z * v.z + v.w * v.w;
#pragma unroll
    for (int o = 16; o > 0; o >>= 1) {
        s += __shfl_xor_sync(0xffffffffu, s, o);
        q += __shfl_xor_sync(0xffffffffu, q, o);
    }
    if ((tid & 31) == 0) { rs[tid >> 5] = s; rq[tid >> 5] = q; }
    __syncthreads();
    if (tid == 0) {
        float S = 0.f, Q = 0.f;
#pragma unroll
        for (int w = 0; w < 8; w++) { S += rs[w]; Q += rq[w]; }
        float mu  = S * (1.0f / 1024.0f);
        float var = Q * (1.0f / 1024.0f) - mu * mu;
        s_mu   = mu;
        s_rstd = rsqrtf(var + 1e-6f);
    }
    __syncthreads();
    float mu = s_mu, r = s_rstd;
    float4 g  = *(const float4*)(gamma + tid * 4);
    float4 bb = *(const float4*)(beta + tid * 4);
    float4 o4;
    o4.x = (v.x - mu) * r * g.x + bb.x;
    o4.y = (v.y - mu) * r * g.y + bb.y;
    o4.z = (v.z - mu) * r * g.z + bb.z;
    o4.w = (v.w - mu) * r * g.w + bb.w;
    *(float4*)(out + (size_t)row * 1024 + tid * 4) = o4;
}

// ---------------------------------------------------------------------------
// Launch sequence
// ---------------------------------------------------------------------------
extern "C" void kernel_launch(void* const* d_in, const int* in_sizes, int n_in,
                              void* d_out, int out_size)
{
    (void)in_sizes; (void)n_in; (void)out_size;
    const float* h     = (const float*)d_in[0];
    const float* Wq    = (const float*)d_in[1];
    const float* bq    = (const float*)d_in[2];
    const float* Wk    = (const float*)d_in[3];
    const float* bk    = (const float*)d_in[4];
    const float* Wv    = (const float*)d_in[5];
    const float* bv    = (const float*)d_in[6];
    const float* Wo    = (const float*)d_in[7];
    const float* bo    = (const float*)d_in[8];
    const float* gamma = (const float*)d_in[9];
    const float* beta  = (const float*)d_in[10];
    float* out = (float*)d_out;

    float* tp;
    cudaGetSymbolAddress((void**)&tp, g_tmp);

    __nv_bfloat16 *hh, *hl, *ch, *cl;
    __nv_bfloat16 *qh, *ql, *kh, *kl, *vh, *vl;
    __nv_bfloat16 *wqh, *wql, *wkh, *wkl, *wvh, *wvl, *woh, *wol;
    cudaGetSymbolAddress((void**)&hh,  g_hh);  cudaGetSymbolAddress((void**)&hl,  g_hl);
    cudaGetSymbolAddress((void**)&ch,  g_ch);  cudaGetSymbolAddress((void**)&cl,  g_cl);
    cudaGetSymbolAddress((void**)&qh,  g_Qh);  cudaGetSymbolAddress((void**)&ql,  g_Ql);
    cudaGetSymbolAddress((void**)&kh,  g_Kh);  cudaGetSymbolAddress((void**)&kl,  g_Kl);
    cudaGetSymbolAddress((void**)&vh,  g_Vh);  cudaGetSymbolAddress((void**)&vl,  g_Vl);
    cudaGetSymbolAddress((void**)&wqh, g_wqh); cudaGetSymbolAddress((void**)&wql, g_wql);
    cudaGetSymbolAddress((void**)&wkh, g_wkh); cudaGetSymbolAddress((void**)&wkl, g_wkl);
    cudaGetSymbolAddress((void**)&wvh, g_wvh); cudaGetSymbolAddress((void**)&wvl, g_wvl);
    cudaGetSymbolAddress((void**)&woh, g_woh); cudaGetSymbolAddress((void**)&wol, g_wol);

    cudaFuncSetAttribute(gemm_mma<0>, cudaFuncAttributeMaxDynamicSharedMemorySize, GEMM_SMEM);
    cudaFuncSetAttribute(gemm_mma<1>, cudaFuncAttributeMaxDynamicSharedMemorySize, GEMM_SMEM);
    cudaFuncSetAttribute(gemm_mma<2>, cudaFuncAttributeMaxDynamicSharedMemorySize, GEMM_SMEM);
    cudaFuncSetAttribute(attn_mma,    cudaFuncAttributeMaxDynamicSharedMemorySize, ATT_SMEM);

    split8<<<ROW_ELEMS / 2048, 256>>>(h,  hh,  hl);
    split8<<<W_ELEMS  / 2048, 256>>>(Wq, wqh, wql);
    split8<<<W_ELEMS  / 2048, 256>>>(Wk, wkh, wkl);
    split8<<<W_ELEMS  / 2048, 256>>>(Wv, wvh, wvl);
    split8<<<W_ELEMS  / 2048, 256>>>(Wo, woh, wol);

    dim3 gg(1024 / 128, 4096 / 128);  // (8, 32)
    gemm_mma<0><<<gg, 256, GEMM_SMEM>>>(hh, hl, wqh, wql, bq, nullptr, nullptr, qh, ql);
    gemm_mma<1><<<gg, 256, GEMM_SMEM>>>(hh, hl, wkh, wkl, bk, nullptr, nullptr, kh, kl);
    gemm_mma<1><<<gg, 256, GEMM_SMEM>>>(hh, hl, wvh, wvl, bv, nullptr, nullptr, vh, vl);

    attn_mma<<<dim3(16, 32), 256, ATT_SMEM>>>(qh, ql, kh, kl, vh, vl, ch, cl);

    gemm_mma<2><<<gg, 256, GEMM_SMEM>>>(ch, cl, woh, wol, bo, h, tp, nullptr, nullptr);

    ln_kernel<<<4096, 256>>>(tp, gamma, beta, out);
}